// round 16
// baseline (speedup 1.0000x reference)
#include <cuda_runtime.h>
#include <cstdint>

// SoftQuantize: x (8192,512) fp32, c (4,256) fp32, sigma (1,) fp32 -> out (8192,512) fp32
// rows = 8192*128 subvectors of dim 4; softmax over 256 centers.
//
// HYBRID: fp32 packed-FMA dots + ex2 on the SM pipes; the accumulation GEMM
//   out_cols = q(1Mx256) @ B(256x8),  B = [k1*c0..k1*c3 | ones | 0 0 0]
// on the TENSOR pipe via mma.sync.m16n8k8.row.col.f32.tf32.tf32.f32.
// Warp tile = 16 rows x 256 centers. Lane (gid=lane/4, tq=lane%4) computes
// p for rows (gid, gid+8) x centers (8s+tq, 8s+tq+4) per k8 step s -- exactly
// the m16n8k8 A-fragment layout. Row-pair f32x2 packed dot produces both rows'
// args in one chain. B is precomputed in smem as ready-made fragments
// (cvt.rna.tf32). D accumulators: n0..n3 (k1-scaled) + den (ones column).
//
// Unshifted args: arg_l = k1*(z.c_l) + beta_l; softmax shift cancels in
// num/den. A-operand tf32 truncation hits numerator and denominator with the
// SAME per-term factor (one register feeds all columns) -> ratio bias cancels.
// Guard: den in [1e-30,1e36] (|num| <= ~50*den); inf/NaN fail -> exact
// two-pass scalar fallback per row (P ~ 2.5e-4).

#define LQ  256
#define TPB 128
#define NROWS (8192*128)
#define NSTEP 32
#define DMIN 1e-30f
#define DMAX 1e36f

typedef unsigned long long u64;
typedef unsigned int u32;

static __device__ __forceinline__ u64 pk(float lo, float hi) {
    u64 r; asm("mov.b64 %0, {%1, %2};" : "=l"(r) : "f"(lo), "f"(hi)); return r;
}
static __device__ __forceinline__ void unpk(u64 v, float& lo, float& hi) {
    asm("mov.b64 {%0, %1}, %2;" : "=f"(lo), "=f"(hi) : "l"(v));
}
static __device__ __forceinline__ u64 f2fma(u64 a, u64 b, u64 c) {
    u64 d; asm("fma.rn.f32x2 %0, %1, %2, %3;" : "=l"(d) : "l"(a), "l"(b), "l"(c)); return d;
}
static __device__ __forceinline__ float ex2f(float x) {
    float y; asm("ex2.approx.f32 %0, %1;" : "=f"(y) : "f"(x)); return y;
}
static __device__ __forceinline__ float rcpf(float x) {
    float y; asm("rcp.approx.f32 %0, %1;" : "=f"(y) : "f"(x)); return y;
}
static __device__ __forceinline__ u32 tf32rna(float x) {
    u32 r; asm("cvt.rna.tf32.f32 %0, %1;" : "=r"(r) : "f"(x)); return r;
}

// Exact two-pass softmax for one row (rare tail fallback).
// scb[l*3+0] = {pk(k1c0),pk(k1c1)}, scb[l*3+1] = {pk(k1c2),pk(k1c3)},
// scb[l*3+2].x = pk(beta,beta). Low halves hold the scalar values.
static __device__ __noinline__ void fb_row(const float4* __restrict__ x4,
                                           float4* __restrict__ out4,
                                           int row,
                                           const ulonglong2* scb,
                                           float invk1)
{
    float4 z = x4[row];
    float m = -1.0e30f;
    for (int l = 0; l < LQ; ++l) {
        const float* fA = (const float*)&scb[l*3];      // [0]=k1c0, [2]=k1c1
        const float* fB = (const float*)&scb[l*3 + 1];  // [0]=k1c2, [2]=k1c3
        float beta = ((const float*)&scb[l*3 + 2])[0];
        float arg = fmaf(z.x, fA[0], beta);
        arg = fmaf(z.y, fA[2], arg);
        arg = fmaf(z.z, fB[0], arg);
        arg = fmaf(z.w, fB[2], arg);
        m = fmaxf(m, arg);
    }
    float den = 0.f, n0 = 0.f, n1 = 0.f, n2 = 0.f, n3 = 0.f;
    for (int l = 0; l < LQ; ++l) {
        const float* fA = (const float*)&scb[l*3];
        const float* fB = (const float*)&scb[l*3 + 1];
        float beta = ((const float*)&scb[l*3 + 2])[0];
        float arg = fmaf(z.x, fA[0], beta);
        arg = fmaf(z.y, fA[2], arg);
        arg = fmaf(z.z, fB[0], arg);
        arg = fmaf(z.w, fB[2], arg);
        float p = ex2f(arg - m);
        den += p;
        n0 = fmaf(p, fA[0], n0);
        n1 = fmaf(p, fA[2], n1);
        n2 = fmaf(p, fB[0], n2);
        n3 = fmaf(p, fB[2], n3);
    }
    float sf = rcpf(den) * invk1;
    out4[row] = make_float4(n0*sf, n1*sf, n2*sf, n3*sf);
}

__global__ __launch_bounds__(TPB, 8)
void softq_kernel(const float4* __restrict__ x4,
                  const float*  __restrict__ c,
                  const float*  __restrict__ sigma,
                  float4*       __restrict__ out4)
{
    __shared__ ulonglong2 scb[LQ * 3];      // 12KB: per-center A-side codebook (fp32, dup-packed)
    __shared__ uint2      sB[NSTEP * 32];   // 8KB: B fragments (tf32), [step][lane]

    const float LOG2E = 1.4426950408889634f;
    float s  = fmaxf(sigma[0], 0.0f) + 1e-4f;
    float sl = s * LOG2E;
    float k1 = 2.0f * sl;

    int t = threadIdx.x;
    // A-side codebook: full fp32, k1-scaled, duplicated pairs; beta packed
    #pragma unroll
    for (int i = t; i < LQ; i += TPB) {
        float c0 = c[i], c1 = c[LQ + i], c2 = c[2*LQ + i], c3 = c[3*LQ + i];
        float csq  = c0*c0 + c1*c1 + c2*c2 + c3*c3;
        float beta = -sl * csq;
        scb[i*3 + 0].x = pk(k1*c0, k1*c0);
        scb[i*3 + 0].y = pk(k1*c1, k1*c1);
        scb[i*3 + 1].x = pk(k1*c2, k1*c2);
        scb[i*3 + 1].y = pk(k1*c3, k1*c3);
        scb[i*3 + 2].x = pk(beta, beta);
        scb[i*3 + 2].y = 0ull;
    }
    // B fragments: b0=(k=lane%4, n=lane/4), b1=(k=lane%4+4, n=lane/4),
    // center = 8*step + k; cols 0..3 = k1*c_m, col 4 = 1, cols 5..7 = 0.
    #pragma unroll
    for (int idx = t; idx < NSTEP * 32; idx += TPB) {
        int st = idx >> 5, ln = idx & 31;
        int k = ln & 3, col = ln >> 2;
        int l0 = 8*st + k, l1 = l0 + 4;
        float v0, v1;
        if (col < 4)       { v0 = k1 * c[col*LQ + l0]; v1 = k1 * c[col*LQ + l1]; }
        else if (col == 4) { v0 = 1.0f; v1 = 1.0f; }
        else               { v0 = 0.0f; v1 = 0.0f; }
        sB[idx] = make_uint2(tf32rna(v0), tf32rna(v1));
    }
    __syncthreads();

    const int warp = t >> 5, lane = t & 31;
    const int gid = lane >> 2, tq = lane & 3;
    const int R = blockIdx.x * 64 + warp * 16;
    const int r0 = R + gid, r1 = r0 + 8;

    // z row-pair packed: lanes of f32x2 = rows (r0, r1)
    u64 zz0, zz1, zz2, zz3;
    {
        float4 za = x4[r0];
        float4 zb = x4[r1];
        zz0 = pk(za.x, zb.x);
        zz1 = pk(za.y, zb.y);
        zz2 = pk(za.z, zb.z);
        zz3 = pk(za.w, zb.w);
    }

    float d0 = 0.f, d1 = 0.f, d2 = 0.f, d3 = 0.f;

    const ulonglong2* scbq = scb + tq * 3;       // this lane's base center = tq
    const uint2*      sBl  = sB + lane;

    #pragma unroll 2
    for (int st = 0; st < NSTEP; ++st) {
        // center kc0 = 8*st + tq
        ulonglong2 pA = scbq[24*st + 0];
        ulonglong2 pB = scbq[24*st + 1];
        u64 bb0       = scbq[24*st + 2].x;
        u64 dp = f2fma(zz0, pA.x, bb0);
        dp     = f2fma(zz1, pA.y, dp);
        dp     = f2fma(zz2, pB.x, dp);
        dp     = f2fma(zz3, pB.y, dp);
        float aL0, aH0; unpk(dp, aL0, aH0);
        u32 a0 = __float_as_uint(ex2f(aL0));     // p(r0, kc0)
        u32 a1 = __float_as_uint(ex2f(aH0));     // p(r1, kc0)

        // center kc1 = kc0 + 4
        ulonglong2 qA = scbq[24*st + 12];
        ulonglong2 qB = scbq[24*st + 13];
        u64 bb1       = scbq[24*st + 14].x;
        u64 dq = f2fma(zz0, qA.x, bb1);
        dq     = f2fma(zz1, qA.y, dq);
        dq     = f2fma(zz2, qB.x, dq);
        dq     = f2fma(zz3, qB.y, dq);
        float aL1, aH1; unpk(dq, aL1, aH1);
        u32 a2 = __float_as_uint(ex2f(aL1));     // p(r0, kc1)
        u32 a3 = __float_as_uint(ex2f(aH1));     // p(r1, kc1)

        uint2 bf = sBl[st * 32];
        asm volatile(
            "mma.sync.aligned.m16n8k8.row.col.f32.tf32.tf32.f32 "
            "{%0,%1,%2,%3}, {%4,%5,%6,%7}, {%8,%9}, {%0,%1,%2,%3};"
            : "+f"(d0), "+f"(d1), "+f"(d2), "+f"(d3)
            : "r"(a0), "r"(a1), "r"(a2), "r"(a3), "r"(bf.x), "r"(bf.y));
    }

    // D layout: d0=(row r0, col 2tq), d1=(r0, 2tq+1), d2=(r1, 2tq), d3=(r1, 2tq+1)
    // Writer lane tq==0 gathers: n0,n1 own; n2,n3 from tq==1; den from tq==2.
    int l4 = lane & ~3;
    float e0 = __shfl_sync(0xffffffffu, d0, l4 + 1);   // n2 (r0)
    float e1 = __shfl_sync(0xffffffffu, d1, l4 + 1);   // n3 (r0)
    float e2 = __shfl_sync(0xffffffffu, d2, l4 + 1);   // n2 (r1)
    float e3 = __shfl_sync(0xffffffffu, d3, l4 + 1);   // n3 (r1)
    float w0 = __shfl_sync(0xffffffffu, d0, l4 + 2);   // den (r0)
    float w1 = __shfl_sync(0xffffffffu, d2, l4 + 2);   // den (r1)

    if (tq == 0) {
        float invk1 = 1.0f / k1;
        if (!((w0 >= DMIN) && (w0 <= DMAX))) {         // NaN/inf fail too
            fb_row(x4, out4, r0, scb, invk1);
        } else {
            float sf = rcpf(w0) * invk1;
            out4[r0] = make_float4(d0*sf, d1*sf, e0*sf, e1*sf);
        }
        if (!((w1 >= DMIN) && (w1 <= DMAX))) {
            fb_row(x4, out4, r1, scb, invk1);
        } else {
            float sf = rcpf(w1) * invk1;
            out4[r1] = make_float4(d2*sf, d3*sf, e2*sf, e3*sf);
        }
    }
}

extern "C" void kernel_launch(void* const* d_in, const int* in_sizes, int n_in,
                              void* d_out, int out_size)
{
    const float* x     = (const float*)d_in[0];
    const float* c     = (const float*)d_in[1];
    const float* sigma = (const float*)d_in[2];
    float* out = (float*)d_out;

    int blocks = NROWS / 64;   // 16384 (64 rows per 128-thread block)
    softq_kernel<<<blocks, TPB>>>((const float4*)x, c, sigma, (float4*)out);
}